// round 11
// baseline (speedup 1.0000x reference)
#include <cuda_runtime.h>
#include <cuda_bf16.h>
#include <math.h>
#include <stdint.h>

#define D_MODEL 1024
#define NHEAD   16
#define DK      64
#define BATCH   2
#define SEQ     2048
#define MROWS   (BATCH * SEQ)
#define NBH     (BATCH * NHEAD)
#define OUT_ELEMS ((size_t)MROWS * D_MODEL)

typedef __nv_bfloat16 bf16;

// Scratch (no cudaMalloc allowed). All interchange in split bf16 hi/lo.
__device__ bf16 g_Ah[MROWS * D_MODEL];
__device__ bf16 g_Al[MROWS * D_MODEL];
__device__ bf16 g_Wh[D_MODEL * D_MODEL];
__device__ bf16 g_Wl[D_MODEL * D_MODEL];
__device__ bf16 g_Qh[MROWS * D_MODEL];
__device__ bf16 g_Ql[MROWS * D_MODEL];
__device__ bf16 g_Kh[MROWS * D_MODEL];
__device__ bf16 g_Kl[MROWS * D_MODEL];
__device__ bf16 g_Vh[MROWS * D_MODEL];
__device__ bf16 g_Vl[MROWS * D_MODEL];
__device__ bf16 g_Ch[MROWS * D_MODEL];
__device__ bf16 g_Cl[MROWS * D_MODEL];
__device__ bf16 g_Ph[(size_t)NBH * SEQ * SEQ];
__device__ bf16 g_Pl[(size_t)NBH * SEQ * SEQ];
__device__ float g_s[NBH * SEQ];

// ---------------------------------------------------------------------------
__device__ __forceinline__ unsigned smaddr(const void* p) {
    return (unsigned)__cvta_generic_to_shared(p);
}

__device__ __forceinline__ void cpa16(unsigned dst, const void* src) {
    asm volatile("cp.async.cg.shared.global [%0], [%1], 16;" :: "r"(dst), "l"(src));
}
#define CP_COMMIT() asm volatile("cp.async.commit_group;" ::: "memory")
#define CP_WAIT(n)  asm volatile("cp.async.wait_group %0;" :: "n"(n) : "memory")

__device__ __forceinline__ void splitstore4(float4 v, bf16* hb, bf16* lb) {
    float f[4] = {v.x, v.y, v.z, v.w};
    unsigned h[2], l[2];
    #pragma unroll
    for (int i = 0; i < 2; i++) {
        bf16 a = __float2bfloat16(f[2*i]);
        bf16 b = __float2bfloat16(f[2*i+1]);
        h[i] = ((unsigned)__bfloat16_as_ushort(b) << 16) | __bfloat16_as_ushort(a);
        bf16 ra = __float2bfloat16(f[2*i]   - __bfloat162float(a));
        bf16 rb = __float2bfloat16(f[2*i+1] - __bfloat162float(b));
        l[i] = ((unsigned)__bfloat16_as_ushort(rb) << 16) | __bfloat16_as_ushort(ra);
    }
    *(uint2*)hb = make_uint2(h[0], h[1]);
    *(uint2*)lb = make_uint2(l[0], l[1]);
}

__device__ __forceinline__ void split2w(float a, float b, unsigned& hw, unsigned& lw) {
    bf16 ha = __float2bfloat16(a), hb = __float2bfloat16(b);
    hw = ((unsigned)__bfloat16_as_ushort(hb) << 16) | __bfloat16_as_ushort(ha);
    bf16 la = __float2bfloat16(a - __bfloat162float(ha));
    bf16 lb = __float2bfloat16(b - __bfloat162float(hb));
    lw = ((unsigned)__bfloat16_as_ushort(lb) << 16) | __bfloat16_as_ushort(la);
}

__device__ __forceinline__ float bflo(unsigned w) {
    return __bfloat162float(__ushort_as_bfloat16((unsigned short)(w & 0xffffu)));
}
__device__ __forceinline__ float bfhi(unsigned w) {
    return __bfloat162float(__ushort_as_bfloat16((unsigned short)(w >> 16)));
}

__device__ __forceinline__ void mma_bf16(float* c, const unsigned* a, const unsigned* b) {
    asm volatile(
        "mma.sync.aligned.m16n8k16.row.col.f32.bf16.bf16.f32 "
        "{%0,%1,%2,%3},{%4,%5,%6,%7},{%8,%9},{%0,%1,%2,%3};"
        : "+f"(c[0]), "+f"(c[1]), "+f"(c[2]), "+f"(c[3])
        : "r"(a[0]), "r"(a[1]), "r"(a[2]), "r"(a[3]), "r"(b[0]), "r"(b[1]));
}

__device__ __forceinline__ void ldsm4(unsigned& r0, unsigned& r1, unsigned& r2,
                                      unsigned& r3, unsigned a) {
    asm volatile("ldmatrix.sync.aligned.m8n8.x4.shared.b16 {%0,%1,%2,%3}, [%4];"
        : "=r"(r0), "=r"(r1), "=r"(r2), "=r"(r3) : "r"(a));
}
__device__ __forceinline__ void ldsm4t(unsigned& r0, unsigned& r1, unsigned& r2,
                                       unsigned& r3, unsigned a) {
    asm volatile("ldmatrix.sync.aligned.m8n8.x4.trans.shared.b16 {%0,%1,%2,%3}, [%4];"
        : "=r"(r0), "=r"(r1), "=r"(r2), "=r"(r3) : "r"(a));
}

// Warp tile 64(m) x (NJ*16)(n), one k16 slab, 3-term bf16.
template<int SA, int SB, bool BT, int NJ>
__device__ __forceinline__ void warp_mma_k16(
    float (*acc)[NJ * 2][4],
    const bf16* Ah, const bf16* Al, const bf16* Bh, const bf16* Bl,
    int m0base, int n0base, int k0a, int k0b, int lane)
{
    int g = lane >> 3, r = lane & 7;
    unsigned ah[4][4], al[4][4], bh[NJ * 2][2], bl[NJ * 2][2];

    int arow = (g & 1) * 8 + r, acol = k0a + (g >> 1) * 8;
    #pragma unroll
    for (int mi = 0; mi < 4; mi++) {
        int row = m0base + mi * 16 + arow;
        ldsm4(ah[mi][0], ah[mi][1], ah[mi][2], ah[mi][3], smaddr(Ah + row * SA + acol));
        ldsm4(al[mi][0], al[mi][1], al[mi][2], al[mi][3], smaddr(Al + row * SA + acol));
    }
    #pragma unroll
    for (int nj = 0; nj < NJ; nj++) {
        int n0 = n0base + nj * 16;
        unsigned q0, q1, q2, q3;
        if (BT) {
            int row = k0b + (g & 1) * 8 + r;
            int col = n0 + (g >> 1) * 8;
            ldsm4t(q0, q1, q2, q3, smaddr(Bh + row * SB + col));
            bh[nj*2][0] = q0; bh[nj*2][1] = q1; bh[nj*2+1][0] = q2; bh[nj*2+1][1] = q3;
            ldsm4t(q0, q1, q2, q3, smaddr(Bl + row * SB + col));
            bl[nj*2][0] = q0; bl[nj*2][1] = q1; bl[nj*2+1][0] = q2; bl[nj*2+1][1] = q3;
        } else {
            int row = n0 + (g >> 1) * 8 + r;
            int col = k0b + (g & 1) * 8;
            ldsm4(q0, q1, q2, q3, smaddr(Bh + row * SB + col));
            bh[nj*2][0] = q0; bh[nj*2][1] = q1; bh[nj*2+1][0] = q2; bh[nj*2+1][1] = q3;
            ldsm4(q0, q1, q2, q3, smaddr(Bl + row * SB + col));
            bl[nj*2][0] = q0; bl[nj*2][1] = q1; bl[nj*2+1][0] = q2; bl[nj*2+1][1] = q3;
        }
    }
    #pragma unroll
    for (int mi = 0; mi < 4; mi++)
        #pragma unroll
        for (int ni = 0; ni < NJ * 2; ni++) {
            mma_bf16(acc[mi][ni], ah[mi], bh[ni]);
            mma_bf16(acc[mi][ni], ah[mi], bl[ni]);
            mma_bf16(acc[mi][ni], al[mi], bh[ni]);
        }
}

// ---------------------------------------------------------------------------
// Pre-pass 1: split fp32 array into bf16 hi/lo. 8 elems/thread.
// ---------------------------------------------------------------------------
__global__ __launch_bounds__(256) void conv_split(
    const float* __restrict__ X, bf16* __restrict__ H, bf16* __restrict__ L)
{
    size_t e = ((size_t)blockIdx.x * 256 + threadIdx.x) * 8;
    float4 v0 = *(const float4*)(X + e);
    float4 v1 = *(const float4*)(X + e + 4);
    bf16 hb[8], lb[8];
    splitstore4(v0, hb, lb);
    splitstore4(v1, hb + 4, lb + 4);
    *(uint4*)(H + e) = *(uint4*)hb;
    *(uint4*)(L + e) = *(uint4*)lb;
}

// ---------------------------------------------------------------------------
// Pre-pass 2: W [K,N] fp32 -> W^T hi/lo [N,K] bf16.
// ---------------------------------------------------------------------------
__global__ void convT(const float* __restrict__ W, bf16* __restrict__ H,
                      bf16* __restrict__ L)
{
    __shared__ float t[32][33];
    int k0 = blockIdx.x * 32, n0 = blockIdx.y * 32;
    int tx = threadIdx.x, ty = threadIdx.y;
    #pragma unroll
    for (int j = 0; j < 4; j++)
        t[ty + 8 * j][tx] = W[(size_t)(k0 + ty + 8 * j) * D_MODEL + n0 + tx];
    __syncthreads();
    #pragma unroll
    for (int j = 0; j < 4; j++) {
        int n = ty + 8 * j;
        float f = t[tx][n];
        bf16 h = __float2bfloat16(f);
        bf16 l = __float2bfloat16(f - __bfloat162float(h));
        H[(size_t)(n0 + n) * D_MODEL + k0 + tx] = h;
        L[(size_t)(n0 + n) * D_MODEL + k0 + tx] = l;
    }
}

// ---------------------------------------------------------------------------
// Projection GEMM (cp.async, bf16 in, bf16-split or fp32 out).
// Y[m][n] = sum_k A[m][k] * Wt[n][k] + bias[n]. BM=128, BN=128, BK=64.
// 3 smem stages (1 barrier/stage, depth-2 prefetch).
// Stage layout (bf16 elems): Ah[128][72] | Al | Bh[128][72] | Bl  = 36864.
// ---------------------------------------------------------------------------
#define PJ_STAGE_E 36864
#define PJ_SMEM_BYTES (3 * PJ_STAGE_E * 2)

template<bool SPLIT>
__global__ __launch_bounds__(256) void proj_cp(
    const bf16* __restrict__ Ahg, const bf16* __restrict__ Alg,
    const bf16* __restrict__ Bhg, const bf16* __restrict__ Blg,
    const float* __restrict__ bias,
    float* __restrict__ Yf, bf16* __restrict__ Yh, bf16* __restrict__ Yl)
{
    extern __shared__ bf16 smb[];
    int tid = threadIdx.x, lane = tid & 31, warp = tid >> 5;
    int warpM = warp >> 2, warpN = warp & 3;
    int rowBase = blockIdx.y * 128, colBase = blockIdx.x * 128;

    auto issue = [&](int s) {
        bf16* st = smb + (s % 3) * PJ_STAGE_E;
        int k0 = s * 64;
        #pragma unroll
        for (int i = 0; i < 16; i++) {
            int arr = i >> 2;
            int rc = tid + (i & 3) * 256;          // 0..1023
            int row = rc >> 3, c = rc & 7;
            const bf16* src;
            if (arr == 0)      src = Ahg + (size_t)(rowBase + row) * D_MODEL + k0 + c * 8;
            else if (arr == 1) src = Alg + (size_t)(rowBase + row) * D_MODEL + k0 + c * 8;
            else if (arr == 2) src = Bhg + (size_t)(colBase + row) * D_MODEL + k0 + c * 8;
            else               src = Blg + (size_t)(colBase + row) * D_MODEL + k0 + c * 8;
            cpa16(smaddr(st + arr * 9216 + row * 72 + c * 8), src);
        }
        CP_COMMIT();
    };

    issue(0);
    issue(1);

    float acc[4][4][4] = {};
    const int NST = D_MODEL / 64;   // 16
    for (int s = 0; s < NST; s++) {
        CP_WAIT(1);
        __syncthreads();
        if (s + 2 < NST) issue(s + 2);
        bf16* st = smb + (s % 3) * PJ_STAGE_E;
        #pragma unroll
        for (int kk = 0; kk < 4; kk++)
            warp_mma_k16<72, 72, false, 2>(acc, st, st + 9216, st + 18432, st + 27648,
                                           warpM * 64, warpN * 32, kk * 16, kk * 16, lane);
        __syncthreads();
    }

    int r = lane >> 2, t = lane & 3;
    #pragma unroll
    for (int mi = 0; mi < 4; mi++) {
        int row0 = rowBase + warpM * 64 + mi * 16 + r;
        #pragma unroll
        for (int ni = 0; ni < 4; ni++) {
            int col = colBase + warpN * 32 + ni * 8 + t * 2;
            float2 b2 = *(const float2*)&bias[col];
            float v00 = acc[mi][ni][0] + b2.x, v01 = acc[mi][ni][1] + b2.y;
            float v10 = acc[mi][ni][2] + b2.x, v11 = acc[mi][ni][3] + b2.y;
            if (SPLIT) {
                unsigned hw, lw;
                split2w(v00, v01, hw, lw);
                *(unsigned*)&Yh[(size_t)row0 * D_MODEL + col] = hw;
                *(unsigned*)&Yl[(size_t)row0 * D_MODEL + col] = lw;
                split2w(v10, v11, hw, lw);
                *(unsigned*)&Yh[(size_t)(row0 + 8) * D_MODEL + col] = hw;
                *(unsigned*)&Yl[(size_t)(row0 + 8) * D_MODEL + col] = lw;
            } else {
                *(float2*)&Yf[(size_t)row0 * D_MODEL + col] = make_float2(v00, v01);
                *(float2*)&Yf[(size_t)(row0 + 8) * D_MODEL + col] = make_float2(v10, v11);
            }
        }
    }
}

// ---------------------------------------------------------------------------
// scores: e = exp(score), written as bf16 hi/lo to g_Ph/g_Pl, + row sums g_s.
// Q tile hoisted via cp.async; K staged 4-deep (1 barrier/stage).
// smem (bf16 elems): Qh[128][72] 0 | Ql 9216 | K stages at 18432, each 18432
//   (Kh 9216 + Kl 9216) x 4. RedS floats at byte 184320.
// ---------------------------------------------------------------------------
#define SC_KB_E 18432
#define SC_KSTAGE_E 18432
#define SC_RS_BYTE 184320
#define SC_SMEM_BYTES (SC_RS_BYTE + 2048)

__global__ __launch_bounds__(256) void scores_cp(
    const bf16* __restrict__ Qhg, const bf16* __restrict__ Qlg,
    const bf16* __restrict__ Khg, const bf16* __restrict__ Klg,
    bf16* __restrict__ Ph, bf16* __restrict__ Pl)
{
    extern __shared__ bf16 smb[];
    float (*RedS)[128] = (float(*)[128])((char*)smb + SC_RS_BYTE);

    int tid = threadIdx.x, lane = tid & 31, warp = tid >> 5;
    int warpM = warp >> 2, warpN = warp & 3;
    int qBase = blockIdx.x * 128;
    int bh = blockIdx.y, b = bh >> 4, h = bh & 15;
    int r = lane >> 2, t = lane & 3;

    // Q hoist (part of group 0)
    {
        #pragma unroll
        for (int i = 0; i < 8; i++) {
            int arr = i >> 2;
            int rc = tid + (i & 3) * 256;
            int row = rc >> 3, c = rc & 7;
            const bf16* src = (arr ? Qlg : Qhg)
                + (size_t)(b * SEQ + qBase + row) * D_MODEL + h * DK + c * 8;
            cpa16(smaddr(smb + arr * 9216 + row * 72 + c * 8), src);
        }
    }
    auto issueK = [&](int st) {
        bf16* base = smb + SC_KB_E + (st & 3) * SC_KSTAGE_E;
        #pragma unroll
        for (int i = 0; i < 8; i++) {
            int arr = i >> 2;
            int rc = tid + (i & 3) * 256;
            int row = rc >> 3, c = rc & 7;
            const bf16* src = (arr ? Klg : Khg)
                + (size_t)(b * SEQ + st * 128 + row) * D_MODEL + h * DK + c * 8;
            cpa16(smaddr(base + arr * 9216 + row * 72 + c * 8), src);
        }
    };

    issueK(0); CP_COMMIT();           // G0 = Q + K0
    issueK(1); CP_COMMIT();           // G1
    issueK(2); CP_COMMIT();           // G2

    float rs[8];
    #pragma unroll
    for (int j = 0; j < 8; j++) rs[j] = 0.0f;
    const float scale = 0.125f;

    for (int st = 0; st < 16; st++) {
        CP_WAIT(2);
        __syncthreads();
        if (st + 3 < 16) { issueK(st + 3); CP_COMMIT(); }

        float acc[4][4][4] = {};
        bf16* Kst = smb + SC_KB_E + (st & 3) * SC_KSTAGE_E;
        #pragma unroll
        for (int kk = 0; kk < 4; kk++)
            warp_mma_k16<72, 72, false, 2>(acc, smb, smb + 9216, Kst, Kst + 9216,
                                           warpM * 64, warpN * 32, kk * 16, kk * 16, lane);

        int sBase = st * 128;
        #pragma unroll
        for (int mi = 0; mi < 4; mi++) {
            #pragma unroll
            for (int hh = 0; hh < 2; hh++) {
                int row = qBase + warpM * 64 + mi * 16 + hh * 8 + r;
                size_t rowOff = ((size_t)bh * SEQ + row) * SEQ;
                int j = mi * 2 + hh;
                float add = 0.0f;
                #pragma unroll
                for (int ni = 0; ni < 4; ni++) {
                    float e0 = __expf(acc[mi][ni][hh * 2 + 0] * scale);
                    float e1 = __expf(acc[mi][ni][hh * 2 + 1] * scale);
                    int col = sBase + warpN * 32 + ni * 8 + t * 2;
                    unsigned hw, lw;
                    split2w(e0, e1, hw, lw);
                    *(unsigned*)&Ph[rowOff + col] = hw;
                    *(unsigned*)&Pl[rowOff + col] = lw;
                    add += e0 + e1;
                }
                rs[j] += add;
            }
        }
    }

    #pragma unroll
    for (int off = 1; off <= 2; off <<= 1)
        #pragma unroll
        for (int j = 0; j < 8; j++)
            rs[j] += __shfl_xor_sync(0xFFFFFFFFu, rs[j], off);
    if (t == 0) {
        #pragma unroll
        for (int mi = 0; mi < 4; mi++)
            #pragma unroll
            for (int hh = 0; hh < 2; hh++) {
                int row = warpM * 64 + mi * 16 + hh * 8 + r;
                RedS[warpN][row] = rs[mi * 2 + hh];
            }
    }
    __syncthreads();
    if (tid < 128) {
        float s = RedS[0][tid] + RedS[1][tid] + RedS[2][tid] + RedS[3][tid];
        g_s[(size_t)bh * SEQ + qBase + tid] = s;
    }
}

// ---------------------------------------------------------------------------
// ctx: MMA on raw e (bf16 hi/lo), scale by 1/s in epilogue; writes the final
// fp32 attn p = (eh+el)*inv from staged smem; outputs ctx as bf16 hi/lo.
// BM=256(q), BN=64(dk), BK=32(s). 4 stages, 1 barrier/stage, depth-3.
// Stage (bf16 elems): Ah[256][40] 10240 | Al 10240 | Bh[32][72] 2304 | Bl 2304
//   = 25088. smI floats at byte 200704.
// ---------------------------------------------------------------------------
#define CT_STAGE_E 25088
#define CT_SMI_BYTE 200704
#define CT_SMEM_BYTES (CT_SMI_BYTE + 1024)

__global__ __launch_bounds__(256) void ctx_cp(
    const bf16* __restrict__ Phg, const bf16* __restrict__ Plg,
    const bf16* __restrict__ Vhg, const bf16* __restrict__ Vlg,
    float* __restrict__ attn, bf16* __restrict__ Ch, bf16* __restrict__ Cl)
{
    extern __shared__ bf16 smb[];
    float* smI = (float*)((char*)smb + CT_SMI_BYTE);

    int tid = threadIdx.x, lane = tid & 31, warp = tid >> 5;
    int warpM = warp >> 1, warpN = warp & 1;
    int qBase = blockIdx.x * 256;
    int bh = blockIdx.y, b = bh >> 4, h = bh & 15;
    int r = lane >> 2, t = lane & 3;

    smI[tid] = 1.0f / g_s[(size_t)bh * SEQ + qBase + tid];

    auto issue = [&](int st) {
        bf16* base = smb + (st & 3) * CT_STAGE_E;
        // A: e tile 256 x 32 (hi/lo)
        #pragma unroll
        for (int i = 0; i < 8; i++) {
            int arr = i >> 2;
            int rc = tid + (i & 3) * 256;          // 0..1023
            int row = rc >> 2, c = rc & 3;
            const bf16* src = (arr ? Plg : Phg)
                + ((size_t)bh * SEQ + qBase + row) * SEQ + st * 32 + c * 8;
            cpa16(smaddr(base + arr * 10240 + row * 40 + c * 8), src);
        }
        // B: V tile 32 x 64 (hi/lo)
        #pragma unroll
        for (int i = 0; i < 2; i++) {
            int row = tid >> 3, c = tid & 7;
            const bf16* src = (i ? Vlg : Vhg)
                + (size_t)(b * SEQ + st * 32 + row) * D_MODEL + h * DK + c * 8;
            cpa16(smaddr(base + 20480 + i * 2304 + row * 72 + c * 8), src);
        }
        CP_COMMIT();
    };

    issue(0); issue(1); issue(2);

    float acc[4][4][4] = {};
    const int NST = SEQ / 32;   // 64
    for (int st = 0; st < NST; st++) {
        CP_WAIT(2);
        __syncthreads();
        if (st + 3 < NST) issue(st + 3);

        bf16* base = smb + (st & 3) * CT_STAGE_E;
        warp_mma_k16<40, 72, true, 2>(acc, base, base + 10240, base + 20480, base + 22784,
                                      warpM * 64, warpN * 32, 0, 0, lane);
        warp_mma_k16<40, 72, true, 2>(acc, base, base + 10240, base + 20480, base + 22784,
                                      warpM * 64, warpN * 32, 16, 16, lane);

        // p-write: row tid, 32 elems of this stage from staged smem.
        {
            float inv = smI[tid];
            float* arow = attn + ((size_t)bh * SEQ + qBase + tid) * SEQ + st * 32;
            const bf16* Ah = base + tid * 40;
            const bf16* Al = base + 10240 + tid * 40;
            #pragma unroll
            for (int c4 = 0; c4 < 4; c4++) {
                uint4 hv = *(const uint4*)(Ah + c4 * 8);
                uint4 lv = *(const uint4*)(Al + c4 * 8);
                unsigned hw[4] = {hv.x, hv.y, hv.z, hv.w};
                unsigned lw[4] = {lv.x, lv.y, lv.z, lv.w};
                float p[8];
                #pragma unroll
                for (int j = 0; j < 4; j++) {
                    p[2*j]   = (bflo(hw[j]) + bflo(lw[j])) * inv;
                    p[2*j+1] = (bfhi(hw[j]) + bfhi(lw[j])) * inv;
                }
                *(float4*)(arow + c4 * 8)     = make_float4(p[0], p[1], p[2], p[3]);
                *(float4*)(arow + c4 * 8 + 4) = make_float4(p[4], p[5], p[6], p[7]);
            }
        }
    }

    #pragma unroll
    for (int mi = 0; mi < 4; mi++) {
        int rowL0 = warpM * 64 + mi * 16 + r;
        float i0 = smI[rowL0], i1 = smI[rowL0 + 8];
        #pragma unroll
        for (int ni = 0; ni < 4; ni++) {
            int col = h * DK + warpN * 32 + ni * 8 + t * 2;
            size_t o0 = (size_t)(b * SEQ + qBase + rowL0) * D_MODEL + col;
            size_t o1 = (size_t)(b * SEQ + qBase + rowL0 + 8) * D_MODEL + col;
            unsigned hw, lw;
            split2w(acc[mi][ni][0] * i0, acc[mi][ni][1] * i0, hw, lw);
            *(unsigned*)&Ch[o0] = hw;
            *(unsigned*)&Cl[o0] = lw;
            split2w(acc[mi][ni][2] * i1, acc[mi][ni][3] * i1, hw, lw);
            *(unsigned*)&Ch[o1] = hw;
            *(unsigned*)&Cl[o1] = lw;
        }
    }
}

// ---------------------------------------------------------------------------
extern "C" void kernel_launch(void* const* d_in, const int* in_sizes, int n_in,
                              void* d_out, int out_size)
{
    const float* query = (const float*)d_in[0];
    const float* key   = (const float*)d_in[1];
    const float* value = (const float*)d_in[2];
    const float* Wq = (const float*)d_in[3];
    const float* bq = (const float*)d_in[4];
    const float* Wk = (const float*)d_in[5];
    const float* bk = (const float*)d_in[6];
    const float* Wv = (const float*)d_in[7];
    const float* bv = (const float*)d_in[8];
    const float* Wo = (const float*)d_in[9];
    const float* bo = (const float*)d_in[10];

    float* out  = (float*)d_out;
    float* attn = (float*)d_out + OUT_ELEMS;

    bf16 *Ahp, *Alp, *Whp, *Wlp, *Qhp, *Qlp, *Khp, *Klp, *Vhp, *Vlp, *Chp, *Clp, *Php, *Plp;
    cudaGetSymbolAddress((void**)&Ahp, g_Ah);
    cudaGetSymbolAddress((void**)&Alp, g_Al);
    cudaGetSymbolAddress((void**)&Whp, g_Wh);
    cudaGetSymbolAddress((void**)&Wlp, g_Wl);
    cudaGetSymbolAddress((void**)&Qhp, g_Qh);
    cudaGetSymbolAddress((void**)&Qlp, g_Ql);
    cudaGetSymbolAddress((void**)&Khp, g_Kh);
    cudaGetSymbolAddress((void**)&Klp, g_Kl);
    cudaGetSymbolAddress((void**)&Vhp, g_Vh);
    cudaGetSymbolAddress((void**)&Vlp, g_Vl);
    cudaGetSymbolAddress((void**)&Chp, g_Ch);
    cudaGetSymbolAddress((void**)&Clp, g_Cl);
    cudaGetSymbolAddress((void**)&Php, g_Ph);
    cudaGetSymbolAddress((void**)&Plp, g_Pl);

    static int configured = 0;
    if (!configured) {
        cudaFuncSetAttribute(proj_cp<true>, cudaFuncAttributeMaxDynamicSharedMemorySize,
                             PJ_SMEM_BYTES);
        cudaFuncSetAttribute(proj_cp<false>, cudaFuncAttributeMaxDynamicSharedMemorySize,
                             PJ_SMEM_BYTES);
        cudaFuncSetAttribute(scores_cp, cudaFuncAttributeMaxDynamicSharedMemorySize,
                             SC_SMEM_BYTES);
        cudaFuncSetAttribute(ctx_cp, cudaFuncAttributeMaxDynamicSharedMemorySize,
                             CT_SMEM_BYTES);
        configured = 1;
    }

    dim3 gProj(D_MODEL / 128, MROWS / 128);   // (8, 32)
    dim3 gScores(SEQ / 128, NBH);             // (16, 32)
    dim3 gCtx(SEQ / 256, NBH);                // (8, 32)
    dim3 gT(D_MODEL / 32, D_MODEL / 32);
    dim3 bT(32, 8);
    int nConvBlocks = (MROWS * D_MODEL) / 2048;

    // Q projection
    conv_split<<<nConvBlocks, 256>>>(query, Ahp, Alp);
    convT<<<gT, bT>>>(Wq, Whp, Wlp);
    proj_cp<true><<<gProj, 256, PJ_SMEM_BYTES>>>(Ahp, Alp, Whp, Wlp, bq, nullptr, Qhp, Qlp);
    // K projection
    conv_split<<<nConvBlocks, 256>>>(key, Ahp, Alp);
    convT<<<gT, bT>>>(Wk, Whp, Wlp);
    proj_cp<true><<<gProj, 256, PJ_SMEM_BYTES>>>(Ahp, Alp, Whp, Wlp, bk, nullptr, Khp, Klp);
    // V projection
    conv_split<<<nConvBlocks, 256>>>(value, Ahp, Alp);
    convT<<<gT, bT>>>(Wv, Whp, Wlp);
    proj_cp<true><<<gProj, 256, PJ_SMEM_BYTES>>>(Ahp, Alp, Whp, Wlp, bv, nullptr, Vhp, Vlp);

    // Attention
    scores_cp<<<gScores, 256, SC_SMEM_BYTES>>>(Qhp, Qlp, Khp, Klp, Php, Plp);
    ctx_cp<<<gCtx, 256, CT_SMEM_BYTES>>>(Php, Plp, Vhp, Vlp, attn, Chp, Clp);

    // Output projection (fp32 out)
    convT<<<gT, bT>>>(Wo, Whp, Wlp);
    proj_cp<false><<<gProj, 256, PJ_SMEM_BYTES>>>(Chp, Clp, Whp, Wlp, bo, out, nullptr, nullptr);
}

// round 13
// speedup vs baseline: 1.9039x; 1.9039x over previous
#include <cuda_runtime.h>
#include <cuda_bf16.h>
#include <math.h>
#include <stdint.h>

#define D_MODEL 1024
#define NHEAD   16
#define DK      64
#define BATCH   2
#define SEQ     2048
#define MROWS   (BATCH * SEQ)
#define NBH     (BATCH * NHEAD)
#define OUT_ELEMS ((size_t)MROWS * D_MODEL)

typedef __nv_bfloat16 bf16;

// Scratch (no cudaMalloc allowed). Interchange in split bf16 hi/lo.
__device__ bf16 g_Ah[MROWS * D_MODEL];
__device__ bf16 g_Al[MROWS * D_MODEL];
__device__ bf16 g_Wh[D_MODEL * D_MODEL];
__device__ bf16 g_Wl[D_MODEL * D_MODEL];
__device__ bf16 g_Qh[MROWS * D_MODEL];
__device__ bf16 g_Ql[MROWS * D_MODEL];
__device__ bf16 g_Kh[MROWS * D_MODEL];
__device__ bf16 g_Kl[MROWS * D_MODEL];
__device__ bf16 g_Vh[MROWS * D_MODEL];
__device__ bf16 g_Vl[MROWS * D_MODEL];
__device__ bf16 g_Ch[MROWS * D_MODEL];
__device__ bf16 g_Cl[MROWS * D_MODEL];
__device__ float g_s[NBH * SEQ];

// ---------------------------------------------------------------------------
__device__ __forceinline__ unsigned smaddr(const void* p) {
    return (unsigned)__cvta_generic_to_shared(p);
}

__device__ __forceinline__ void cpa16(unsigned dst, const void* src) {
    asm volatile("cp.async.cg.shared.global [%0], [%1], 16;" :: "r"(dst), "l"(src));
}
#define CP_COMMIT() asm volatile("cp.async.commit_group;" ::: "memory")
#define CP_WAIT(n)  asm volatile("cp.async.wait_group %0;" :: "n"(n) : "memory")

__device__ __forceinline__ void splitstore4(float4 v, bf16* hb, bf16* lb) {
    float f[4] = {v.x, v.y, v.z, v.w};
    unsigned h[2], l[2];
    #pragma unroll
    for (int i = 0; i < 2; i++) {
        bf16 a = __float2bfloat16(f[2*i]);
        bf16 b = __float2bfloat16(f[2*i+1]);
        h[i] = ((unsigned)__bfloat16_as_ushort(b) << 16) | __bfloat16_as_ushort(a);
        bf16 ra = __float2bfloat16(f[2*i]   - __bfloat162float(a));
        bf16 rb = __float2bfloat16(f[2*i+1] - __bfloat162float(b));
        l[i] = ((unsigned)__bfloat16_as_ushort(rb) << 16) | __bfloat16_as_ushort(ra);
    }
    *(uint2*)hb = make_uint2(h[0], h[1]);
    *(uint2*)lb = make_uint2(l[0], l[1]);
}

__device__ __forceinline__ void split2w(float a, float b, unsigned& hw, unsigned& lw) {
    bf16 ha = __float2bfloat16(a), hb = __float2bfloat16(b);
    hw = ((unsigned)__bfloat16_as_ushort(hb) << 16) | __bfloat16_as_ushort(ha);
    bf16 la = __float2bfloat16(a - __bfloat162float(ha));
    bf16 lb = __float2bfloat16(b - __bfloat162float(hb));
    lw = ((unsigned)__bfloat16_as_ushort(lb) << 16) | __bfloat16_as_ushort(la);
}

__device__ __forceinline__ void mma_bf16(float* c, const unsigned* a, const unsigned* b) {
    asm volatile(
        "mma.sync.aligned.m16n8k16.row.col.f32.bf16.bf16.f32 "
        "{%0,%1,%2,%3},{%4,%5,%6,%7},{%8,%9},{%0,%1,%2,%3};"
        : "+f"(c[0]), "+f"(c[1]), "+f"(c[2]), "+f"(c[3])
        : "r"(a[0]), "r"(a[1]), "r"(a[2]), "r"(a[3]), "r"(b[0]), "r"(b[1]));
}

__device__ __forceinline__ void ldsm4(unsigned& r0, unsigned& r1, unsigned& r2,
                                      unsigned& r3, unsigned a) {
    asm volatile("ldmatrix.sync.aligned.m8n8.x4.shared.b16 {%0,%1,%2,%3}, [%4];"
        : "=r"(r0), "=r"(r1), "=r"(r2), "=r"(r3) : "r"(a));
}
__device__ __forceinline__ void ldsm4t(unsigned& r0, unsigned& r1, unsigned& r2,
                                       unsigned& r3, unsigned a) {
    asm volatile("ldmatrix.sync.aligned.m8n8.x4.trans.shared.b16 {%0,%1,%2,%3}, [%4];"
        : "=r"(r0), "=r"(r1), "=r"(r2), "=r"(r3) : "r"(a));
}

// Warp tile 64(m) x (NJ*16)(n), one k16 slab, 3-term bf16.
template<int SA, int SB, bool BT, int NJ>
__device__ __forceinline__ void warp_mma_k16(
    float (*acc)[NJ * 2][4],
    const bf16* Ah, const bf16* Al, const bf16* Bh, const bf16* Bl,
    int m0base, int n0base, int k0a, int k0b, int lane)
{
    int g = lane >> 3, r = lane & 7;
    unsigned ah[4][4], al[4][4], bh[NJ * 2][2], bl[NJ * 2][2];

    int arow = (g & 1) * 8 + r, acol = k0a + (g >> 1) * 8;
    #pragma unroll
    for (int mi = 0; mi < 4; mi++) {
        int row = m0base + mi * 16 + arow;
        ldsm4(ah[mi][0], ah[mi][1], ah[mi][2], ah[mi][3], smaddr(Ah + row * SA + acol));
        ldsm4(al[mi][0], al[mi][1], al[mi][2], al[mi][3], smaddr(Al + row * SA + acol));
    }
    #pragma unroll
    for (int nj = 0; nj < NJ; nj++) {
        int n0 = n0base + nj * 16;
        unsigned q0, q1, q2, q3;
        if (BT) {
            int row = k0b + (g & 1) * 8 + r;
            int col = n0 + (g >> 1) * 8;
            ldsm4t(q0, q1, q2, q3, smaddr(Bh + row * SB + col));
            bh[nj*2][0] = q0; bh[nj*2][1] = q1; bh[nj*2+1][0] = q2; bh[nj*2+1][1] = q3;
            ldsm4t(q0, q1, q2, q3, smaddr(Bl + row * SB + col));
            bl[nj*2][0] = q0; bl[nj*2][1] = q1; bl[nj*2+1][0] = q2; bl[nj*2+1][1] = q3;
        } else {
            int row = n0 + (g >> 1) * 8 + r;
            int col = k0b + (g & 1) * 8;
            ldsm4(q0, q1, q2, q3, smaddr(Bh + row * SB + col));
            bh[nj*2][0] = q0; bh[nj*2][1] = q1; bh[nj*2+1][0] = q2; bh[nj*2+1][1] = q3;
            ldsm4(q0, q1, q2, q3, smaddr(Bl + row * SB + col));
            bl[nj*2][0] = q0; bl[nj*2][1] = q1; bl[nj*2+1][0] = q2; bl[nj*2+1][1] = q3;
        }
    }
    #pragma unroll
    for (int mi = 0; mi < 4; mi++)
        #pragma unroll
        for (int ni = 0; ni < NJ * 2; ni++) {
            mma_bf16(acc[mi][ni], ah[mi], bh[ni]);
            mma_bf16(acc[mi][ni], ah[mi], bl[ni]);
            mma_bf16(acc[mi][ni], al[mi], bh[ni]);
        }
}

// ---------------------------------------------------------------------------
// Pre-pass 1: split fp32 array into bf16 hi/lo. 8 elems/thread.
// ---------------------------------------------------------------------------
__global__ __launch_bounds__(256) void conv_split(
    const float* __restrict__ X, bf16* __restrict__ H, bf16* __restrict__ L)
{
    size_t e = ((size_t)blockIdx.x * 256 + threadIdx.x) * 8;
    float4 v0 = *(const float4*)(X + e);
    float4 v1 = *(const float4*)(X + e + 4);
    bf16 hb[8], lb[8];
    splitstore4(v0, hb, lb);
    splitstore4(v1, hb + 4, lb + 4);
    *(uint4*)(H + e) = *(uint4*)hb;
    *(uint4*)(L + e) = *(uint4*)lb;
}

// ---------------------------------------------------------------------------
// Pre-pass 2: W [K,N] fp32 -> W^T hi/lo [N,K] bf16.
// ---------------------------------------------------------------------------
__global__ void convT(const float* __restrict__ W, bf16* __restrict__ H,
                      bf16* __restrict__ L)
{
    __shared__ float t[32][33];
    int k0 = blockIdx.x * 32, n0 = blockIdx.y * 32;
    int tx = threadIdx.x, ty = threadIdx.y;
    #pragma unroll
    for (int j = 0; j < 4; j++)
        t[ty + 8 * j][tx] = W[(size_t)(k0 + ty + 8 * j) * D_MODEL + n0 + tx];
    __syncthreads();
    #pragma unroll
    for (int j = 0; j < 4; j++) {
        int n = ty + 8 * j;
        float f = t[tx][n];
        bf16 h = __float2bfloat16(f);
        bf16 l = __float2bfloat16(f - __bfloat162float(h));
        H[(size_t)(n0 + n) * D_MODEL + k0 + tx] = h;
        L[(size_t)(n0 + n) * D_MODEL + k0 + tx] = l;
    }
}

// ---------------------------------------------------------------------------
// Projection GEMM (cp.async, split-bf16 in, split-bf16 or fp32 out).
// Y[m][n] = sum_k A[m][k] * Wt[n][k] + bias[n]. BM=128, BN=128, BK=64.
// 3 smem stages, 1 barrier/stage, depth-2 prefetch.
// Stage (bf16 elems): Ah[128][72] | Al | Bh[128][72] | Bl = 36864.
// ---------------------------------------------------------------------------
#define PJ_STAGE_E 36864
#define PJ_SMEM_BYTES (3 * PJ_STAGE_E * 2)

template<bool SPLIT>
__global__ __launch_bounds__(256) void proj_cp(
    const bf16* __restrict__ Ahg, const bf16* __restrict__ Alg,
    const bf16* __restrict__ Bhg, const bf16* __restrict__ Blg,
    const float* __restrict__ bias,
    float* __restrict__ Yf, bf16* __restrict__ Yh, bf16* __restrict__ Yl)
{
    extern __shared__ bf16 smb[];
    int tid = threadIdx.x, lane = tid & 31, warp = tid >> 5;
    int warpM = warp >> 2, warpN = warp & 3;
    int rowBase = blockIdx.y * 128, colBase = blockIdx.x * 128;

    auto issue = [&](int s) {
        bf16* st = smb + (s % 3) * PJ_STAGE_E;
        int k0 = s * 64;
        #pragma unroll
        for (int i = 0; i < 16; i++) {
            int arr = i >> 2;
            int rc = tid + (i & 3) * 256;
            int row = rc >> 3, c = rc & 7;
            const bf16* src;
            if (arr == 0)      src = Ahg + (size_t)(rowBase + row) * D_MODEL + k0 + c * 8;
            else if (arr == 1) src = Alg + (size_t)(rowBase + row) * D_MODEL + k0 + c * 8;
            else if (arr == 2) src = Bhg + (size_t)(colBase + row) * D_MODEL + k0 + c * 8;
            else               src = Blg + (size_t)(colBase + row) * D_MODEL + k0 + c * 8;
            cpa16(smaddr(st + arr * 9216 + row * 72 + c * 8), src);
        }
        CP_COMMIT();
    };

    issue(0);
    issue(1);

    float acc[4][4][4] = {};
    const int NST = D_MODEL / 64;   // 16
    for (int s = 0; s < NST; s++) {
        CP_WAIT(1);
        __syncthreads();
        if (s + 2 < NST) issue(s + 2);
        bf16* st = smb + (s % 3) * PJ_STAGE_E;
        #pragma unroll
        for (int kk = 0; kk < 4; kk++)
            warp_mma_k16<72, 72, false, 2>(acc, st, st + 9216, st + 18432, st + 27648,
                                           warpM * 64, warpN * 32, kk * 16, kk * 16, lane);
        __syncthreads();
    }

    int r = lane >> 2, t = lane & 3;
    #pragma unroll
    for (int mi = 0; mi < 4; mi++) {
        int row0 = rowBase + warpM * 64 + mi * 16 + r;
        #pragma unroll
        for (int ni = 0; ni < 4; ni++) {
            int col = colBase + warpN * 32 + ni * 8 + t * 2;
            float2 b2 = *(const float2*)&bias[col];
            float v00 = acc[mi][ni][0] + b2.x, v01 = acc[mi][ni][1] + b2.y;
            float v10 = acc[mi][ni][2] + b2.x, v11 = acc[mi][ni][3] + b2.y;
            if (SPLIT) {
                unsigned hw, lw;
                split2w(v00, v01, hw, lw);
                *(unsigned*)&Yh[(size_t)row0 * D_MODEL + col] = hw;
                *(unsigned*)&Yl[(size_t)row0 * D_MODEL + col] = lw;
                split2w(v10, v11, hw, lw);
                *(unsigned*)&Yh[(size_t)(row0 + 8) * D_MODEL + col] = hw;
                *(unsigned*)&Yl[(size_t)(row0 + 8) * D_MODEL + col] = lw;
            } else {
                *(float2*)&Yf[(size_t)row0 * D_MODEL + col] = make_float2(v00, v01);
                *(float2*)&Yf[(size_t)(row0 + 8) * D_MODEL + col] = make_float2(v10, v11);
            }
        }
    }
}

// ---------------------------------------------------------------------------
// scores: e = exp(score) (fp32, coalesced) to attn + row sums g_s.
// Pre-split Q hoisted, K staged 4-deep, all via cp.async (zero conversion).
// smem (bf16 elems): Qh 0 | Ql 9216 | K stages at 18432, each 18432 x 4.
// RedS floats at byte 184320.
// ---------------------------------------------------------------------------
#define SC_KB_E 18432
#define SC_KSTAGE_E 18432
#define SC_RS_BYTE 184320
#define SC_SMEM_BYTES (SC_RS_BYTE + 2048)

__global__ __launch_bounds__(256) void scores_cp(
    const bf16* __restrict__ Qhg, const bf16* __restrict__ Qlg,
    const bf16* __restrict__ Khg, const bf16* __restrict__ Klg,
    float* __restrict__ attn)
{
    extern __shared__ bf16 smb[];
    float (*RedS)[128] = (float(*)[128])((char*)smb + SC_RS_BYTE);

    int tid = threadIdx.x, lane = tid & 31, warp = tid >> 5;
    int warpM = warp >> 2, warpN = warp & 3;
    int qBase = blockIdx.x * 128;
    int bh = blockIdx.y, b = bh >> 4, h = bh & 15;
    int r = lane >> 2, t = lane & 3;

    // Q hoist (part of group 0)
    {
        #pragma unroll
        for (int i = 0; i < 8; i++) {
            int arr = i >> 2;
            int rc = tid + (i & 3) * 256;
            int row = rc >> 3, c = rc & 7;
            const bf16* src = (arr ? Qlg : Qhg)
                + (size_t)(b * SEQ + qBase + row) * D_MODEL + h * DK + c * 8;
            cpa16(smaddr(smb + arr * 9216 + row * 72 + c * 8), src);
        }
    }
    auto issueK = [&](int st) {
        bf16* base = smb + SC_KB_E + (st & 3) * SC_KSTAGE_E;
        #pragma unroll
        for (int i = 0; i < 8; i++) {
            int arr = i >> 2;
            int rc = tid + (i & 3) * 256;
            int row = rc >> 3, c = rc & 7;
            const bf16* src = (arr ? Klg : Khg)
                + (size_t)(b * SEQ + st * 128 + row) * D_MODEL + h * DK + c * 8;
            cpa16(smaddr(base + arr * 9216 + row * 72 + c * 8), src);
        }
    };

    issueK(0); CP_COMMIT();    // G0 = Q + K0
    issueK(1); CP_COMMIT();    // G1
    issueK(2); CP_COMMIT();    // G2

    float rs[8];
    #pragma unroll
    for (int j = 0; j < 8; j++) rs[j] = 0.0f;
    const float scale = 0.125f;

    for (int st = 0; st < 16; st++) {
        CP_WAIT(2);
        __syncthreads();
        if (st + 3 < 16) { issueK(st + 3); CP_COMMIT(); }

        float acc[4][4][4] = {};
        bf16* Kst = smb + SC_KB_E + (st & 3) * SC_KSTAGE_E;
        #pragma unroll
        for (int kk = 0; kk < 4; kk++)
            warp_mma_k16<72, 72, false, 2>(acc, smb, smb + 9216, Kst, Kst + 9216,
                                           warpM * 64, warpN * 32, kk * 16, kk * 16, lane);

        int sBase = st * 128;
        #pragma unroll
        for (int mi = 0; mi < 4; mi++) {
            #pragma unroll
            for (int hh = 0; hh < 2; hh++) {
                int row = qBase + warpM * 64 + mi * 16 + hh * 8 + r;
                size_t rowOff = ((size_t)bh * SEQ + row) * SEQ;
                int j = mi * 2 + hh;
                float add = 0.0f;
                #pragma unroll
                for (int ni = 0; ni < 4; ni++) {
                    float e0 = __expf(acc[mi][ni][hh * 2 + 0] * scale);
                    float e1 = __expf(acc[mi][ni][hh * 2 + 1] * scale);
                    int col = sBase + warpN * 32 + ni * 8 + t * 2;
                    *(float2*)&attn[rowOff + col] = make_float2(e0, e1);
                    add += e0 + e1;
                }
                rs[j] += add;
            }
        }
    }

    #pragma unroll
    for (int off = 1; off <= 2; off <<= 1)
        #pragma unroll
        for (int j = 0; j < 8; j++)
            rs[j] += __shfl_xor_sync(0xFFFFFFFFu, rs[j], off);
    if (t == 0) {
        #pragma unroll
        for (int mi = 0; mi < 4; mi++)
            #pragma unroll
            for (int hh = 0; hh < 2; hh++) {
                int row = warpM * 64 + mi * 16 + hh * 8 + r;
                RedS[warpN][row] = rs[mi * 2 + hh];
            }
    }
    __syncthreads();
    if (tid < 128) {
        float s = RedS[0][tid] + RedS[1][tid] + RedS[2][tid] + RedS[3][tid];
        g_s[(size_t)bh * SEQ + qBase + tid] = s;
    }
}

// ---------------------------------------------------------------------------
// ctx: p = e/s (coalesced fp32 attn in/out, A split in-kernel), V via cp.async
// pre-split; ctx output as split bf16. BM=256(q), BN=64(dk), BK=32(s),
// double-buffered, one barrier per stage.
// Stage (bf16 elems): Ah[256][40] 10240 | Al 10240 | Bh[32][72] 2304 | Bl 2304
//   = 25088. smI floats at byte 100352.
// ---------------------------------------------------------------------------
#define CT_STAGE_E 25088
#define CT_SMI_BYTE 100352
#define CT_SMEM_BYTES (CT_SMI_BYTE + 1024)

__global__ __launch_bounds__(256) void ctx_hy(
    float* __restrict__ attn,
    const bf16* __restrict__ Vhg, const bf16* __restrict__ Vlg,
    bf16* __restrict__ Ch, bf16* __restrict__ Cl)
{
    extern __shared__ bf16 smb[];
    float* smI = (float*)((char*)smb + CT_SMI_BYTE);

    int tid = threadIdx.x, lane = tid & 31, warp = tid >> 5;
    int warpM = warp >> 1, warpN = warp & 1;
    int qBase = blockIdx.x * 256;
    int bh = blockIdx.y, b = bh >> 4, h = bh & 15;
    int r = lane >> 2, t = lane & 3;

    smI[tid] = 1.0f / g_s[(size_t)bh * SEQ + qBase + tid];
    __syncthreads();   // smI visible before astore uses it

    float* Ab = attn + ((size_t)bh * SEQ + qBase) * SEQ;

    auto issueV = [&](int st, int buf) {
        bf16* base = smb + buf * CT_STAGE_E;
        int row = tid >> 3, c = tid & 7;
        const bf16* srcH = Vhg + (size_t)(b * SEQ + st * 32 + row) * D_MODEL + h * DK + c * 8;
        const bf16* srcL = Vlg + (size_t)(b * SEQ + st * 32 + row) * D_MODEL + h * DK + c * 8;
        cpa16(smaddr(base + 20480 + row * 72 + c * 8), srcH);
        cpa16(smaddr(base + 22784 + row * 72 + c * 8), srcL);
        CP_COMMIT();
    };

    float4 av[8];
    auto aload = [&](int kpos) {
        #pragma unroll
        for (int i = 0; i < 8; i++) {
            int e = tid + i * 256;
            av[i] = *(const float4*)(Ab + (size_t)(e >> 3) * SEQ + kpos * 32 + (e & 7) * 4);
        }
    };
    auto astore = [&](int buf, int kpos) {
        bf16* Ah = smb + buf * CT_STAGE_E;
        bf16* Al = Ah + 10240;
        #pragma unroll
        for (int i = 0; i < 8; i++) {
            int e = tid + i * 256;
            int m = e >> 3, k = (e & 7) * 4;
            float mI = smI[m];
            float4 p = make_float4(av[i].x * mI, av[i].y * mI,
                                   av[i].z * mI, av[i].w * mI);
            *(float4*)(Ab + (size_t)m * SEQ + kpos * 32 + k) = p;
            splitstore4(p, Ah + m * 40 + k, Al + m * 40 + k);
        }
    };

    issueV(0, 0);
    aload(0);
    astore(0, 0);
    CP_WAIT(0);
    __syncthreads();

    float acc[4][4][4] = {};
    const int NST = SEQ / 32;   // 64
    for (int s = 0; s < NST; s++) {
        int cur = s & 1;
        if (s + 1 < NST) { issueV(s + 1, cur ^ 1); aload(s + 1); }

        bf16* base = smb + cur * CT_STAGE_E;
        warp_mma_k16<40, 72, true, 2>(acc, base, base + 10240, base + 20480, base + 22784,
                                      warpM * 64, warpN * 32, 0, 0, lane);
        warp_mma_k16<40, 72, true, 2>(acc, base, base + 10240, base + 20480, base + 22784,
                                      warpM * 64, warpN * 32, 16, 16, lane);

        if (s + 1 < NST) { astore(cur ^ 1, s + 1); CP_WAIT(0); }
        __syncthreads();
    }

    #pragma unroll
    for (int mi = 0; mi < 4; mi++) {
        int rowL0 = warpM * 64 + mi * 16 + r;
        #pragma unroll
        for (int ni = 0; ni < 4; ni++) {
            int col = h * DK + warpN * 32 + ni * 8 + t * 2;
            size_t o0 = (size_t)(b * SEQ + qBase + rowL0) * D_MODEL + col;
            size_t o1 = (size_t)(b * SEQ + qBase + rowL0 + 8) * D_MODEL + col;
            unsigned hw, lw;
            split2w(acc[mi][ni][0], acc[mi][ni][1], hw, lw);
            *(unsigned*)&Ch[o0] = hw;
            *(unsigned*)&Cl[o0] = lw;
            split2w(acc[mi][ni][2], acc[mi][ni][3], hw, lw);
            *(unsigned*)&Ch[o1] = hw;
            *(unsigned*)&Cl[o1] = lw;
        }
    }
}

// ---------------------------------------------------------------------------
extern "C" void kernel_launch(void* const* d_in, const int* in_sizes, int n_in,
                              void* d_out, int out_size)
{
    const float* query = (const float*)d_in[0];
    const float* key   = (const float*)d_in[1];
    const float* value = (const float*)d_in[2];
    const float* Wq = (const float*)d_in[3];
    const float* bq = (const float*)d_in[4];
    const float* Wk = (const float*)d_in[5];
    const float* bk = (const float*)d_in[6];
    const float* Wv = (const float*)d_in[7];
    const float* bv = (const float*)d_in[8];
    const float* Wo = (const float*)d_in[9];
    const float* bo = (const float*)d_in[10];

    float* out  = (float*)d_out;
    float* attn = (float*)d_out + OUT_ELEMS;

    bf16 *Ahp, *Alp, *Whp, *Wlp, *Qhp, *Qlp, *Khp, *Klp, *Vhp, *Vlp, *Chp, *Clp;
    cudaGetSymbolAddress((void**)&Ahp, g_Ah);
    cudaGetSymbolAddress((void**)&Alp, g_Al);
    cudaGetSymbolAddress((void**)&Whp, g_Wh);
    cudaGetSymbolAddress((void**)&Wlp, g_Wl);
    cudaGetSymbolAddress((void**)&Qhp, g_Qh);
    cudaGetSymbolAddress((void**)&Qlp, g_Ql);
    cudaGetSymbolAddress((void**)&Khp, g_Kh);
    cudaGetSymbolAddress((void**)&Klp, g_Kl);
    cudaGetSymbolAddress((void**)&Vhp, g_Vh);
    cudaGetSymbolAddress((void**)&Vlp, g_Vl);
    cudaGetSymbolAddress((void**)&Chp, g_Ch);
    cudaGetSymbolAddress((void**)&Clp, g_Cl);

    static int configured = 0;
    if (!configured) {
        cudaFuncSetAttribute(proj_cp<true>, cudaFuncAttributeMaxDynamicSharedMemorySize,
                             PJ_SMEM_BYTES);
        cudaFuncSetAttribute(proj_cp<false>, cudaFuncAttributeMaxDynamicSharedMemorySize,
                             PJ_SMEM_BYTES);
        cudaFuncSetAttribute(scores_cp, cudaFuncAttributeMaxDynamicSharedMemorySize,
                             SC_SMEM_BYTES);
        cudaFuncSetAttribute(ctx_hy, cudaFuncAttributeMaxDynamicSharedMemorySize,
                             CT_SMEM_BYTES);
        configured = 1;
    }

    dim3 gProj(D_MODEL / 128, MROWS / 128);   // (8, 32)
    dim3 gScores(SEQ / 128, NBH);             // (16, 32)
    dim3 gCtx(SEQ / 256, NBH);                // (8, 32)
    dim3 gT(D_MODEL / 32, D_MODEL / 32);
    dim3 bT(32, 8);
    int nConvBlocks = (MROWS * D_MODEL) / 2048;

    // Q projection
    conv_split<<<nConvBlocks, 256>>>(query, Ahp, Alp);
    convT<<<gT, bT>>>(Wq, Whp, Wlp);
    proj_cp<true><<<gProj, 256, PJ_SMEM_BYTES>>>(Ahp, Alp, Whp, Wlp, bq, nullptr, Qhp, Qlp);
    // K projection
    conv_split<<<nConvBlocks, 256>>>(key, Ahp, Alp);
    convT<<<gT, bT>>>(Wk, Whp, Wlp);
    proj_cp<true><<<gProj, 256, PJ_SMEM_BYTES>>>(Ahp, Alp, Whp, Wlp, bk, nullptr, Khp, Klp);
    // V projection
    conv_split<<<nConvBlocks, 256>>>(value, Ahp, Alp);
    convT<<<gT, bT>>>(Wv, Whp, Wlp);
    proj_cp<true><<<gProj, 256, PJ_SMEM_BYTES>>>(Ahp, Alp, Whp, Wlp, bv, nullptr, Vhp, Vlp);

    // Attention
    scores_cp<<<gScores, 256, SC_SMEM_BYTES>>>(Qhp, Qlp, Khp, Klp, attn);
    ctx_hy<<<gCtx, 256, CT_SMEM_BYTES>>>(attn, Vhp, Vlp, Chp, Clp);

    // Output projection (fp32 out)
    convT<<<gT, bT>>>(Wo, Whp, Wlp);
    proj_cp<false><<<gProj, 256, PJ_SMEM_BYTES>>>(Chp, Clp, Whp, Wlp, bo, out, nullptr, nullptr);
}

// round 14
// speedup vs baseline: 1.9098x; 1.0031x over previous
#include <cuda_runtime.h>
#include <cuda_bf16.h>
#include <math.h>
#include <stdint.h>

#define D_MODEL 1024
#define NHEAD   16
#define DK      64
#define BATCH   2
#define SEQ     2048
#define MROWS   (BATCH * SEQ)
#define NBH     (BATCH * NHEAD)
#define OUT_ELEMS ((size_t)MROWS * D_MODEL)
#define MD      ((size_t)MROWS * D_MODEL)
#define DD      ((size_t)D_MODEL * D_MODEL)

typedef __nv_bfloat16 bf16;

// Scratch (no cudaMalloc allowed). Interchange in split bf16 hi/lo.
__device__ bf16 g_Ah[3 * MD];          // split query/key/value
__device__ bf16 g_Al[3 * MD];
__device__ bf16 g_Wh[4 * DD];          // split W^T for q,k,v,o
__device__ bf16 g_Wl[4 * DD];
__device__ bf16 g_Qh[MD];
__device__ bf16 g_Ql[MD];
__device__ bf16 g_Kh[MD];
__device__ bf16 g_Kl[MD];
__device__ bf16 g_Vh[MD];
__device__ bf16 g_Vl[MD];
__device__ bf16 g_Ch[MD];
__device__ bf16 g_Cl[MD];
__device__ float g_s[NBH * SEQ];

// ---------------------------------------------------------------------------
__device__ __forceinline__ unsigned smaddr(const void* p) {
    return (unsigned)__cvta_generic_to_shared(p);
}

__device__ __forceinline__ void cpa16(unsigned dst, const void* src) {
    asm volatile("cp.async.cg.shared.global [%0], [%1], 16;" :: "r"(dst), "l"(src));
}
#define CP_COMMIT() asm volatile("cp.async.commit_group;" ::: "memory")
#define CP_WAIT(n)  asm volatile("cp.async.wait_group %0;" :: "n"(n) : "memory")

__device__ __forceinline__ void splitstore4(float4 v, bf16* hb, bf16* lb) {
    float f[4] = {v.x, v.y, v.z, v.w};
    unsigned h[2], l[2];
    #pragma unroll
    for (int i = 0; i < 2; i++) {
        bf16 a = __float2bfloat16(f[2*i]);
        bf16 b = __float2bfloat16(f[2*i+1]);
        h[i] = ((unsigned)__bfloat16_as_ushort(b) << 16) | __bfloat16_as_ushort(a);
        bf16 ra = __float2bfloat16(f[2*i]   - __bfloat162float(a));
        bf16 rb = __float2bfloat16(f[2*i+1] - __bfloat162float(b));
        l[i] = ((unsigned)__bfloat16_as_ushort(rb) << 16) | __bfloat16_as_ushort(ra);
    }
    *(uint2*)hb = make_uint2(h[0], h[1]);
    *(uint2*)lb = make_uint2(l[0], l[1]);
}

__device__ __forceinline__ void split2w(float a, float b, unsigned& hw, unsigned& lw) {
    bf16 ha = __float2bfloat16(a), hb = __float2bfloat16(b);
    hw = ((unsigned)__bfloat16_as_ushort(hb) << 16) | __bfloat16_as_ushort(ha);
    bf16 la = __float2bfloat16(a - __bfloat162float(ha));
    bf16 lb = __float2bfloat16(b - __bfloat162float(hb));
    lw = ((unsigned)__bfloat16_as_ushort(lb) << 16) | __bfloat16_as_ushort(la);
}

__device__ __forceinline__ void mma_bf16(float* c, const unsigned* a, const unsigned* b) {
    asm volatile(
        "mma.sync.aligned.m16n8k16.row.col.f32.bf16.bf16.f32 "
        "{%0,%1,%2,%3},{%4,%5,%6,%7},{%8,%9},{%0,%1,%2,%3};"
        : "+f"(c[0]), "+f"(c[1]), "+f"(c[2]), "+f"(c[3])
        : "r"(a[0]), "r"(a[1]), "r"(a[2]), "r"(a[3]), "r"(b[0]), "r"(b[1]));
}

__device__ __forceinline__ void ldsm4(unsigned& r0, unsigned& r1, unsigned& r2,
                                      unsigned& r3, unsigned a) {
    asm volatile("ldmatrix.sync.aligned.m8n8.x4.shared.b16 {%0,%1,%2,%3}, [%4];"
        : "=r"(r0), "=r"(r1), "=r"(r2), "=r"(r3) : "r"(a));
}
__device__ __forceinline__ void ldsm4t(unsigned& r0, unsigned& r1, unsigned& r2,
                                       unsigned& r3, unsigned a) {
    asm volatile("ldmatrix.sync.aligned.m8n8.x4.trans.shared.b16 {%0,%1,%2,%3}, [%4];"
        : "=r"(r0), "=r"(r1), "=r"(r2), "=r"(r3) : "r"(a));
}

// Warp tile 64(m) x (NJ*16)(n), one k16 slab, 3-term bf16.
template<int SA, int SB, bool BT, int NJ>
__device__ __forceinline__ void warp_mma_k16(
    float (*acc)[NJ * 2][4],
    const bf16* Ah, const bf16* Al, const bf16* Bh, const bf16* Bl,
    int m0base, int n0base, int k0a, int k0b, int lane)
{
    int g = lane >> 3, r = lane & 7;
    unsigned ah[4][4], al[4][4], bh[NJ * 2][2], bl[NJ * 2][2];

    int arow = (g & 1) * 8 + r, acol = k0a + (g >> 1) * 8;
    #pragma unroll
    for (int mi = 0; mi < 4; mi++) {
        int row = m0base + mi * 16 + arow;
        ldsm4(ah[mi][0], ah[mi][1], ah[mi][2], ah[mi][3], smaddr(Ah + row * SA + acol));
        ldsm4(al[mi][0], al[mi][1], al[mi][2], al[mi][3], smaddr(Al + row * SA + acol));
    }
    #pragma unroll
    for (int nj = 0; nj < NJ; nj++) {
        int n0 = n0base + nj * 16;
        unsigned q0, q1, q2, q3;
        if (BT) {
            int row = k0b + (g & 1) * 8 + r;
            int col = n0 + (g >> 1) * 8;
            ldsm4t(q0, q1, q2, q3, smaddr(Bh + row * SB + col));
            bh[nj*2][0] = q0; bh[nj*2][1] = q1; bh[nj*2+1][0] = q2; bh[nj*2+1][1] = q3;
            ldsm4t(q0, q1, q2, q3, smaddr(Bl + row * SB + col));
            bl[nj*2][0] = q0; bl[nj*2][1] = q1; bl[nj*2+1][0] = q2; bl[nj*2+1][1] = q3;
        } else {
            int row = n0 + (g >> 1) * 8 + r;
            int col = k0b + (g & 1) * 8;
            ldsm4(q0, q1, q2, q3, smaddr(Bh + row * SB + col));
            bh[nj*2][0] = q0; bh[nj*2][1] = q1; bh[nj*2+1][0] = q2; bh[nj*2+1][1] = q3;
            ldsm4(q0, q1, q2, q3, smaddr(Bl + row * SB + col));
            bl[nj*2][0] = q0; bl[nj*2][1] = q1; bl[nj*2+1][0] = q2; bl[nj*2+1][1] = q3;
        }
    }
    #pragma unroll
    for (int mi = 0; mi < 4; mi++)
        #pragma unroll
        for (int ni = 0; ni < NJ * 2; ni++) {
            mma_bf16(acc[mi][ni], ah[mi], bh[ni]);
            mma_bf16(acc[mi][ni], ah[mi], bl[ni]);
            mma_bf16(acc[mi][ni], al[mi], bh[ni]);
        }
}

// ---------------------------------------------------------------------------
// Pre-pass 1: split 3 fp32 arrays into bf16 hi/lo. blockIdx.y picks input.
// ---------------------------------------------------------------------------
__global__ __launch_bounds__(256) void conv_split3(
    const float* __restrict__ X0, const float* __restrict__ X1,
    const float* __restrict__ X2, bf16* __restrict__ H, bf16* __restrict__ L)
{
    int which = blockIdx.y;
    const float* X = which == 0 ? X0 : (which == 1 ? X1 : X2);
    bf16* Hd = H + (size_t)which * MD;
    bf16* Ld = L + (size_t)which * MD;
    size_t e = ((size_t)blockIdx.x * 256 + threadIdx.x) * 8;
    float4 v0 = __ldcs((const float4*)(X + e));
    float4 v1 = __ldcs((const float4*)(X + e + 4));
    bf16 hb[8], lb[8];
    splitstore4(v0, hb, lb);
    splitstore4(v1, hb + 4, lb + 4);
    *(uint4*)(Hd + e) = *(uint4*)hb;
    *(uint4*)(Ld + e) = *(uint4*)lb;
}

// ---------------------------------------------------------------------------
// Pre-pass 2: 4 weights [K,N] fp32 -> W^T hi/lo [N,K] bf16. blockIdx.z picks.
// ---------------------------------------------------------------------------
__global__ void convT4(const float* __restrict__ W0, const float* __restrict__ W1,
                       const float* __restrict__ W2, const float* __restrict__ W3,
                       bf16* __restrict__ H, bf16* __restrict__ L)
{
    __shared__ float t[32][33];
    int which = blockIdx.z;
    const float* W = which == 0 ? W0 : (which == 1 ? W1 : (which == 2 ? W2 : W3));
    bf16* Hd = H + (size_t)which * DD;
    bf16* Ld = L + (size_t)which * DD;
    int k0 = blockIdx.x * 32, n0 = blockIdx.y * 32;
    int tx = threadIdx.x, ty = threadIdx.y;
    #pragma unroll
    for (int j = 0; j < 4; j++)
        t[ty + 8 * j][tx] = W[(size_t)(k0 + ty + 8 * j) * D_MODEL + n0 + tx];
    __syncthreads();
    #pragma unroll
    for (int j = 0; j < 4; j++) {
        int n = ty + 8 * j;
        float f = t[tx][n];
        bf16 h = __float2bfloat16(f);
        bf16 l = __float2bfloat16(f - __bfloat162float(h));
        Hd[(size_t)(n0 + n) * D_MODEL + k0 + tx] = h;
        Ld[(size_t)(n0 + n) * D_MODEL + k0 + tx] = l;
    }
}

// ---------------------------------------------------------------------------
// Projection GEMM (cp.async, split-bf16 in, split-bf16 or fp32 out).
// Y[m][n] = sum_k A[m][k] * Wt[n][k] + bias[n]. BM=128, BN=128, BK=64.
// 3 smem stages, 1 barrier/stage, depth-2 prefetch.
// Stage (bf16 elems): Ah[128][72] | Al | Bh[128][72] | Bl = 36864.
// ---------------------------------------------------------------------------
#define PJ_STAGE_E 36864
#define PJ_SMEM_BYTES (3 * PJ_STAGE_E * 2)

template<bool SPLIT>
__global__ __launch_bounds__(256) void proj_cp(
    const bf16* __restrict__ Ahg, const bf16* __restrict__ Alg,
    const bf16* __restrict__ Bhg, const bf16* __restrict__ Blg,
    const float* __restrict__ bias,
    float* __restrict__ Yf, bf16* __restrict__ Yh, bf16* __restrict__ Yl)
{
    extern __shared__ bf16 smb[];
    int tid = threadIdx.x, lane = tid & 31, warp = tid >> 5;
    int warpM = warp >> 2, warpN = warp & 3;
    int rowBase = blockIdx.y * 128, colBase = blockIdx.x * 128;

    auto issue = [&](int s) {
        bf16* st = smb + (s % 3) * PJ_STAGE_E;
        int k0 = s * 64;
        #pragma unroll
        for (int i = 0; i < 16; i++) {
            int arr = i >> 2;
            int rc = tid + (i & 3) * 256;
            int row = rc >> 3, c = rc & 7;
            const bf16* src;
            if (arr == 0)      src = Ahg + (size_t)(rowBase + row) * D_MODEL + k0 + c * 8;
            else if (arr == 1) src = Alg + (size_t)(rowBase + row) * D_MODEL + k0 + c * 8;
            else if (arr == 2) src = Bhg + (size_t)(colBase + row) * D_MODEL + k0 + c * 8;
            else               src = Blg + (size_t)(colBase + row) * D_MODEL + k0 + c * 8;
            cpa16(smaddr(st + arr * 9216 + row * 72 + c * 8), src);
        }
        CP_COMMIT();
    };

    issue(0);
    issue(1);

    float acc[4][4][4] = {};
    const int NST = D_MODEL / 64;   // 16
    for (int s = 0; s < NST; s++) {
        CP_WAIT(1);
        __syncthreads();
        if (s + 2 < NST) issue(s + 2);
        bf16* st = smb + (s % 3) * PJ_STAGE_E;
        #pragma unroll
        for (int kk = 0; kk < 4; kk++)
            warp_mma_k16<72, 72, false, 2>(acc, st, st + 9216, st + 18432, st + 27648,
                                           warpM * 64, warpN * 32, kk * 16, kk * 16, lane);
        __syncthreads();
    }

    int r = lane >> 2, t = lane & 3;
    #pragma unroll
    for (int mi = 0; mi < 4; mi++) {
        int row0 = rowBase + warpM * 64 + mi * 16 + r;
        #pragma unroll
        for (int ni = 0; ni < 4; ni++) {
            int col = colBase + warpN * 32 + ni * 8 + t * 2;
            float2 b2 = *(const float2*)&bias[col];
            float v00 = acc[mi][ni][0] + b2.x, v01 = acc[mi][ni][1] + b2.y;
            float v10 = acc[mi][ni][2] + b2.x, v11 = acc[mi][ni][3] + b2.y;
            if (SPLIT) {
                unsigned hw, lw;
                split2w(v00, v01, hw, lw);
                *(unsigned*)&Yh[(size_t)row0 * D_MODEL + col] = hw;
                *(unsigned*)&Yl[(size_t)row0 * D_MODEL + col] = lw;
                split2w(v10, v11, hw, lw);
                *(unsigned*)&Yh[(size_t)(row0 + 8) * D_MODEL + col] = hw;
                *(unsigned*)&Yl[(size_t)(row0 + 8) * D_MODEL + col] = lw;
            } else {
                *(float2*)&Yf[(size_t)row0 * D_MODEL + col] = make_float2(v00, v01);
                *(float2*)&Yf[(size_t)(row0 + 8) * D_MODEL + col] = make_float2(v10, v11);
            }
        }
    }
}

// ---------------------------------------------------------------------------
// scores: e = exp(score) (fp32, coalesced, streaming store) + row sums g_s.
// Pre-split Q hoisted, K staged 4-deep, all via cp.async (zero conversion).
// smem (bf16 elems): Qh 0 | Ql 9216 | K stages at 18432, each 18432 x 4.
// RedS floats at byte 184320.
// ---------------------------------------------------------------------------
#define SC_KB_E 18432
#define SC_KSTAGE_E 18432
#define SC_RS_BYTE 184320
#define SC_SMEM_BYTES (SC_RS_BYTE + 2048)

__global__ __launch_bounds__(256) void scores_cp(
    const bf16* __restrict__ Qhg, const bf16* __restrict__ Qlg,
    const bf16* __restrict__ Khg, const bf16* __restrict__ Klg,
    float* __restrict__ attn)
{
    extern __shared__ bf16 smb[];
    float (*RedS)[128] = (float(*)[128])((char*)smb + SC_RS_BYTE);

    int tid = threadIdx.x, lane = tid & 31, warp = tid >> 5;
    int warpM = warp >> 2, warpN = warp & 3;
    int qBase = blockIdx.x * 128;
    int bh = blockIdx.y, b = bh >> 4, h = bh & 15;
    int r = lane >> 2, t = lane & 3;

    // Q hoist (part of group 0)
    {
        #pragma unroll
        for (int i = 0; i < 8; i++) {
            int arr = i >> 2;
            int rc = tid + (i & 3) * 256;
            int row = rc >> 3, c = rc & 7;
            const bf16* src = (arr ? Qlg : Qhg)
                + (size_t)(b * SEQ + qBase + row) * D_MODEL + h * DK + c * 8;
            cpa16(smaddr(smb + arr * 9216 + row * 72 + c * 8), src);
        }
    }
    auto issueK = [&](int st) {
        bf16* base = smb + SC_KB_E + (st & 3) * SC_KSTAGE_E;
        #pragma unroll
        for (int i = 0; i < 8; i++) {
            int arr = i >> 2;
            int rc = tid + (i & 3) * 256;
            int row = rc >> 3, c = rc & 7;
            const bf16* src = (arr ? Klg : Khg)
                + (size_t)(b * SEQ + st * 128 + row) * D_MODEL + h * DK + c * 8;
            cpa16(smaddr(base + arr * 9216 + row * 72 + c * 8), src);
        }
    };

    issueK(0); CP_COMMIT();    // G0 = Q + K0
    issueK(1); CP_COMMIT();    // G1
    issueK(2); CP_COMMIT();    // G2

    float rs[8];
    #pragma unroll
    for (int j = 0; j < 8; j++) rs[j] = 0.0f;
    const float scale = 0.125f;

    for (int st = 0; st < 16; st++) {
        CP_WAIT(2);
        __syncthreads();
        if (st + 3 < 16) { issueK(st + 3); CP_COMMIT(); }

        float acc[4][4][4] = {};
        bf16* Kst = smb + SC_KB_E + (st & 3) * SC_KSTAGE_E;
        #pragma unroll
        for (int kk = 0; kk < 4; kk++)
            warp_mma_k16<72, 72, false, 2>(acc, smb, smb + 9216, Kst, Kst + 9216,
                                           warpM * 64, warpN * 32, kk * 16, kk * 16, lane);

        int sBase = st * 128;
        #pragma unroll
        for (int mi = 0; mi < 4; mi++) {
            #pragma unroll
            for (int hh = 0; hh < 2; hh++) {
                int row = qBase + warpM * 64 + mi * 16 + hh * 8 + r;
                size_t rowOff = ((size_t)bh * SEQ + row) * SEQ;
                int j = mi * 2 + hh;
                float add = 0.0f;
                #pragma unroll
                for (int ni = 0; ni < 4; ni++) {
                    float e0 = __expf(acc[mi][ni][hh * 2 + 0] * scale);
                    float e1 = __expf(acc[mi][ni][hh * 2 + 1] * scale);
                    int col = sBase + warpN * 32 + ni * 8 + t * 2;
                    __stcs((float2*)&attn[rowOff + col], make_float2(e0, e1));
                    add += e0 + e1;
                }
                rs[j] += add;
            }
        }
    }

    #pragma unroll
    for (int off = 1; off <= 2; off <<= 1)
        #pragma unroll
        for (int j = 0; j < 8; j++)
            rs[j] += __shfl_xor_sync(0xFFFFFFFFu, rs[j], off);
    if (t == 0) {
        #pragma unroll
        for (int mi = 0; mi < 4; mi++)
            #pragma unroll
            for (int hh = 0; hh < 2; hh++) {
                int row = warpM * 64 + mi * 16 + hh * 8 + r;
                RedS[warpN][row] = rs[mi * 2 + hh];
            }
    }
    __syncthreads();
    if (tid < 128) {
        float s = RedS[0][tid] + RedS[1][tid] + RedS[2][tid] + RedS[3][tid];
        g_s[(size_t)bh * SEQ + qBase + tid] = s;
    }
}

// ---------------------------------------------------------------------------
// ctx: p = e/s (streaming fp32 attn in/out, A split in-kernel), V via cp.async
// pre-split; ctx output as split bf16. BM=256(q), BN=64(dk), BK=32(s),
// double-buffered, one barrier per stage.
// Stage (bf16 elems): Ah[256][40] 10240 | Al 10240 | Bh[32][72] 2304 | Bl 2304
//   = 25088. smI floats at byte 100352.
// ---------------------------------------------------------------------------
#define CT_STAGE_E 25088
#define CT_SMI_BYTE 100352
#define CT_SMEM_BYTES (CT_SMI_BYTE + 1024)

__global__ __launch_bounds__(256) void ctx_hy(
    float* __restrict__ attn,
    const bf16* __restrict__ Vhg, const bf16* __restrict__ Vlg,
    bf16* __restrict__ Ch, bf16* __restrict__ Cl)
{
    extern __shared__ bf16 smb[];
    float* smI = (float*)((char*)smb + CT_SMI_BYTE);

    int tid = threadIdx.x, lane = tid & 31, warp = tid >> 5;
    int warpM = warp >> 1, warpN = warp & 1;
    int qBase = blockIdx.x * 256;
    int bh = blockIdx.y, b = bh >> 4, h = bh & 15;
    int r = lane >> 2, t = lane & 3;

    smI[tid] = 1.0f / g_s[(size_t)bh * SEQ + qBase + tid];
    __syncthreads();   // smI visible before astore uses it

    float* Ab = attn + ((size_t)bh * SEQ + qBase) * SEQ;

    auto issueV = [&](int st, int buf) {
        bf16* base = smb + buf * CT_STAGE_E;
        int row = tid >> 3, c = tid & 7;
        const bf16* srcH = Vhg + (size_t)(b * SEQ + st * 32 + row) * D_MODEL + h * DK + c * 8;
        const bf16* srcL = Vlg + (size_t)(b * SEQ + st * 32 + row) * D_MODEL + h * DK + c * 8;
        cpa16(smaddr(base + 20480 + row * 72 + c * 8), srcH);
        cpa16(smaddr(base + 22784 + row * 72 + c * 8), srcL);
        CP_COMMIT();
    };

    float4 av[8];
    auto aload = [&](int kpos) {
        #pragma unroll
        for (int i = 0; i < 8; i++) {
            int e = tid + i * 256;
            av[i] = __ldcs((const float4*)(Ab + (size_t)(e >> 3) * SEQ + kpos * 32 + (e & 7) * 4));
        }
    };
    auto astore = [&](int buf, int kpos) {
        bf16* Ah = smb + buf * CT_STAGE_E;
        bf16* Al = Ah + 10240;
        #pragma unroll
        for (int i = 0; i < 8; i++) {
            int e = tid + i * 256;
            int m = e >> 3, k = (e & 7) * 4;
            float mI = smI[m];
            float4 p = make_float4(av[i].x * mI, av[i].y * mI,
                                   av[i].z * mI, av[i].w * mI);
            __stcs((float4*)(Ab + (size_t)m * SEQ + kpos * 32 + k), p);
            splitstore4(p, Ah + m * 40 + k, Al + m * 40 + k);
        }
    };

    issueV(0, 0);
    aload(0);
    astore(0, 0);
    CP_WAIT(0);
    __syncthreads();

    float acc[4][4][4] = {};
    const int NST = SEQ / 32;   // 64
    for (int s = 0; s < NST; s++) {
        int cur = s & 1;
        if (s + 1 < NST) { issueV(s + 1, cur ^ 1); aload(s + 1); }

        bf16* base = smb + cur * CT_STAGE_E;
        warp_mma_k16<40, 72, true, 2>(acc, base, base + 10240, base + 20480, base + 22784,
                                      warpM * 64, warpN * 32, 0, 0, lane);
        warp_mma_k16<40, 72, true, 2>(acc, base, base + 10240, base + 20480, base + 22784,
                                      warpM * 64, warpN * 32, 16, 16, lane);

        if (s + 1 < NST) { astore(cur ^ 1, s + 1); CP_WAIT(0); }
        __syncthreads();
    }

    #pragma unroll
    for (int mi = 0; mi < 4; mi++) {
        int rowL0 = warpM * 64 + mi * 16 + r;
        #pragma unroll
        for (int ni = 0; ni < 4; ni++) {
            int col = h * DK + warpN * 32 + ni * 8 + t * 2;
            size_t o0 = (size_t)(b * SEQ + qBase + rowL0) * D_MODEL + col;
            size_t o1 = (size_t)(b * SEQ + qBase + rowL0 + 8) * D_MODEL + col;
            unsigned hw, lw;
            split2w(acc[mi][ni][0], acc[mi][ni][1], hw, lw);
            *(unsigned*)&Ch[o0] = hw;
            *(unsigned*)&Cl[o0] = lw;
            split2w(acc[mi][ni][2], acc[mi][ni][3], hw, lw);
            *(unsigned*)&Ch[o1] = hw;
            *(unsigned*)&Cl[o1] = lw;
        }
    }
}

// ---------------------------------------------------------------------------
extern "C" void kernel_launch(void* const* d_in, const int* in_sizes, int n_in,
                              void* d_out, int out_size)
{
    const float* query = (const float*)d_in[0];
    const float* key   = (const float*)d_in[1];
    const float* value = (const float*)d_in[2];
    const float* Wq = (const float*)d_in[3];
    const float* bq = (const float*)d_in[4];
    const float* Wk = (const float*)d_in[5];
    const float* bk = (const float*)d_in[6];
    const float* Wv = (const float*)d_in[7];
    const float* bv = (const float*)d_in[8];
    const float* Wo = (const float*)d_in[9];
    const float* bo = (const float*)d_in[10];

    float* out  = (float*)d_out;
    float* attn = (float*)d_out + OUT_ELEMS;

    bf16 *Ahp, *Alp, *Whp, *Wlp, *Qhp, *Qlp, *Khp, *Klp, *Vhp, *Vlp, *Chp, *Clp;
    cudaGetSymbolAddress((void**)&Ahp, g_Ah);
    cudaGetSymbolAddress((void**)&Alp, g_Al);
    cudaGetSymbolAddress((void**)&Whp, g_Wh);
    cudaGetSymbolAddress((void**)&Wlp, g_Wl);
    cudaGetSymbolAddress((void**)&Qhp, g_Qh);
    cudaGetSymbolAddress((void**)&Qlp, g_Ql);
    cudaGetSymbolAddress((void**)&Khp, g_Kh);
    cudaGetSymbolAddress((void**)&Klp, g_Kl);
    cudaGetSymbolAddress((void**)&Vhp, g_Vh);
    cudaGetSymbolAddress((void**)&Vlp, g_Vl);
    cudaGetSymbolAddress((void**)&Chp, g_Ch);
    cudaGetSymbolAddress((void**)&Clp, g_Cl);

    static int configured = 0;
    if (!configured) {
        cudaFuncSetAttribute(proj_cp<true>, cudaFuncAttributeMaxDynamicSharedMemorySize,
                             PJ_SMEM_BYTES);
        cudaFuncSetAttribute(proj_cp<false>, cudaFuncAttributeMaxDynamicSharedMemorySize,
                             PJ_SMEM_BYTES);
        cudaFuncSetAttribute(scores_cp, cudaFuncAttributeMaxDynamicSharedMemorySize,
                             SC_SMEM_BYTES);
        cudaFuncSetAttribute(ctx_hy, cudaFuncAttributeMaxDynamicSharedMemorySize,
                             CT_SMEM_BYTES);
        configured = 1;
    }

    dim3 gProj(D_MODEL / 128, MROWS / 128);   // (8, 32)
    dim3 gScores(SEQ / 128, NBH);             // (16, 32)
    dim3 gCtx(SEQ / 256, NBH);                // (8, 32)
    dim3 gConv((MROWS * D_MODEL) / 2048, 3);  // (2048, 3)
    dim3 gT(D_MODEL / 32, D_MODEL / 32, 4);
    dim3 bT(32, 8);

    // All conversions upfront (off the dependency critical path).
    conv_split3<<<gConv, 256>>>(query, key, value, Ahp, Alp);
    convT4<<<gT, bT>>>(Wq, Wk, Wv, Wo, Whp, Wlp);

    // Projections
    proj_cp<true><<<gProj, 256, PJ_SMEM_BYTES>>>(Ahp, Alp, Whp, Wlp, bq,
                                                 nullptr, Qhp, Qlp);
    proj_cp<true><<<gProj, 256, PJ_SMEM_BYTES>>>(Ahp + MD, Alp + MD,
                                                 Whp + DD, Wlp + DD, bk,
                                                 nullptr, Khp, Klp);
    proj_cp<true><<<gProj, 256, PJ_SMEM_BYTES>>>(Ahp + 2 * MD, Alp + 2 * MD,
                                                 Whp + 2 * DD, Wlp + 2 * DD, bv,
                                                 nullptr, Vhp, Vlp);

    // Attention
    scores_cp<<<gScores, 256, SC_SMEM_BYTES>>>(Qhp, Qlp, Khp, Klp, attn);
    ctx_hy<<<gCtx, 256, CT_SMEM_BYTES>>>(attn, Vhp, Vlp, Chp, Clp);

    // Output projection (fp32 out)
    proj_cp<false><<<gProj, 256, PJ_SMEM_BYTES>>>(Chp, Clp, Whp + 3 * DD, Wlp + 3 * DD,
                                                  bo, out, nullptr, nullptr);
}